// round 14
// baseline (speedup 1.0000x reference)
#include <cuda_runtime.h>
#include <cuda_fp16.h>
#include <math.h>
#include <stdint.h>

#define B_    256
#define LAT_  512
#define H_    1024
#define O_    128
#define NPART_ 2
#define MAXT  128

// ---- aux mma.sync GEMM config ----
#define BM 128
#define BN 64
#define BK 32
#define STAGES 4
#define LDS 40
#define SMEM_BYTES (STAGES*(BM+BN)*LDS*2)
enum { EPI_LRELU16 = 0, EPI_H0C0, EPI_LRELU2, EPI_DEC };

// ---- persistent LSTM mainloop config (256 threads, 8 warps, 4 stages) ----
#define BK2   64
#define KH    4
#define ST2   4
#define LDS2  72
#define PSMEM (ST2*(BM+BN)*LDS2*2)   // 110592 B

// ---- device scratch ----
__device__ __align__(16) __half g_Wcat[4096u*2048u];
__device__ __align__(16) float  g_bperm[4096];
__device__ __align__(16) __half g_A[2][B_*2048];
__device__ __align__(16) __half g_hs[(size_t)MAXT*B_*H_];
__device__ __align__(16) __half g_w_l2h [H_*LAT_];
__device__ __align__(16) __half g_w_l2h2[H_*LAT_];
__device__ __align__(16) __half g_w_seq [H_*LAT_];
__device__ __align__(16) __half g_w_mass[H_*LAT_];
__device__ __align__(16) __half g_w_mass2[H_*H_];
__device__ __align__(16) __half g_w_out [O_*H_];
__device__ __align__(16) __half g_enc_h[B_*LAT_];
__device__ __align__(16) __half g_enc_o[B_*LAT_];
__device__ __align__(16) __half g_s1[B_*H_];
__device__ __align__(16) __half g_m1[B_*H_];
__device__ __align__(16) __half g_m2[B_*H_];

// per-my-group barrier state, 128B-separated
__device__ __align__(128) unsigned g_barc2[64];
__device__ __align__(128) unsigned g_barg2[64];

// ---- helpers ----
__device__ __forceinline__ uint32_t smem_u32(const void* p) {
    return (uint32_t)__cvta_generic_to_shared(p);
}
__device__ __forceinline__ void cp16(uint32_t s, const void* g) {
    asm volatile("cp.async.cg.shared.global [%0], [%1], 16;" :: "r"(s), "l"(g));
}
__device__ __forceinline__ void ldsm4(unsigned &r0, unsigned &r1, unsigned &r2, unsigned &r3,
                                      uint32_t addr) {
    asm volatile("ldmatrix.sync.aligned.m8n8.x4.shared.b16 {%0,%1,%2,%3}, [%4];"
                 : "=r"(r0), "=r"(r1), "=r"(r2), "=r"(r3) : "r"(addr));
}
__device__ __forceinline__ void mma16816(float* c, const unsigned* a, unsigned b0, unsigned b1) {
    asm volatile("mma.sync.aligned.m16n8k16.row.col.f32.f16.f16.f32 "
                 "{%0,%1,%2,%3}, {%4,%5,%6,%7}, {%8,%9}, {%0,%1,%2,%3};"
                 : "+f"(c[0]), "+f"(c[1]), "+f"(c[2]), "+f"(c[3])
                 : "r"(a[0]), "r"(a[1]), "r"(a[2]), "r"(a[3]), "r"(b0), "r"(b1));
}
__device__ __forceinline__ float lrelu(float x) { return x > 0.f ? x : 0.01f * x; }
__device__ __forceinline__ float sigm(float x) { return 1.f / (1.f + __expf(-x)); }

// per-group barrier: only the 64 CTAs sharing blockIdx.y must sync
__device__ __forceinline__ void grid_sync_group(unsigned nb, int grp) {
    unsigned* cc = &g_barc2[grp * 32];
    unsigned* gg = &g_barg2[grp * 32];
    __syncthreads();
    if (threadIdx.x == 0) {
        __threadfence();
        unsigned target;
        asm volatile("ld.volatile.global.u32 %0, [%1];" : "=r"(target) : "l"(gg));
        unsigned old = atomicAdd(cc, 1u);
        if (old == nb - 1u) {
            *cc = 0u;
            __threadfence();
            atomicAdd(gg, 1u);
        } else {
            unsigned cur;
            do {
                asm volatile("ld.volatile.global.u32 %0, [%1];" : "=r"(cur) : "l"(gg));
            } while ((int)(cur - target) <= 0);
        }
        __threadfence();
    }
    __syncthreads();
}

// ================= persistent LSTM (exact round-8 schedule, split barrier) =================
__global__ void __launch_bounds__(256, 1)
lstm_persist(const float* __restrict__ bias, float* __restrict__ cst,
             float* __restrict__ hT, __half* __restrict__ hs_all, int T) {
    extern __shared__ __half sm[];
    __half* sA = sm;                        // ST2 * BM * LDS2
    __half* sB = sm + ST2 * BM * LDS2;      // ST2 * BN * LDS2
    __half* hstage = sm;                    // 128 x 24 halfs, reuses sA after mainloop

    const int tid  = threadIdx.x;
    const int lane = tid & 31;
    const int wid  = tid >> 5;
    const int warpM = (wid & 3) * 32;
    const int warpN = (wid >> 2) * 32;
    const int mbase = blockIdx.y * BM;
    const int nbase = blockIdx.x * BN;
    const __half* Bg = g_Wcat + (size_t)nbase * 2048;

    const uint32_t smA = smem_u32(sA);
    const uint32_t smB = smem_u32(sB);
    const int l7  = lane & 7;
    const int grp = lane >> 3;
    const uint32_t aL = smA + (uint32_t)(((warpM + (grp & 1) * 8 + l7) * LDS2 + (grp >> 1) * 8) * 2);
    const uint32_t bL = smB + (uint32_t)(((warpN + (grp >> 1) * 8 + l7) * LDS2 + (grp & 1) * 8) * 2);
    const int r = lane >> 2, q = lane & 3;
    const unsigned NBG = gridDim.x;
    const int myg = blockIdx.y;
    const int KT = 2048 / BK2;              // 32
    const bool evenq = !(q & 1);

    float creg[2][4];
#pragma unroll
    for (int mi = 0; mi < 2; mi++)
#pragma unroll
        for (int ni = 0; ni < 4; ni++) {
            const int m = mbase + warpM + mi * 16 + r + (evenq ? 0 : 8);
            const int u = (nbase + warpN + ni * 8 + 2 * (q & ~1)) >> 2;
            creg[mi][ni] = cst[(size_t)m * H_ + u];
        }

    auto issue_B = [&](int kt, int s) {
        const int ko = kt * BK2;
#pragma unroll
        for (int j = 0; j < 2; j++) {
            const int c = tid + j * 256;
            const int row = c >> 3, ch = c & 7;
            cp16(smB + (uint32_t)(((s * BN + row) * LDS2 + ch * 8) * 2),
                 Bg + (size_t)row * 2048 + ko + ch * 8);
        }
    };

    for (int t = 0; t < T; t++) {
        const __half* Ag = g_A[t & 1] + (size_t)mbase * 2048;
        __half* Anext = g_A[(t + 1) & 1];
        __half* hs = hs_all + (size_t)t * B_ * H_;

        auto issue_A = [&](int kt, int s) {
            const int ko = kt * BK2;
#pragma unroll
            for (int j = 0; j < 4; j++) {
                const int c = tid + j * 256;
                const int row = c >> 3, ch = c & 7;
                cp16(smA + (uint32_t)(((s * BM + row) * LDS2 + ch * 8) * 2),
                     Ag + (size_t)row * 2048 + ko + ch * 8);
            }
        };

        auto load_frag = [&](int s, int kh, unsigned (&fa)[2][4], unsigned (&fb)[2][4]) {
            const uint32_t ab = aL + (uint32_t)(s * BM * LDS2 * 2) + kh * 32;
            ldsm4(fa[0][0], fa[0][1], fa[0][2], fa[0][3], ab);
            ldsm4(fa[1][0], fa[1][1], fa[1][2], fa[1][3], ab + 16 * LDS2 * 2);
            const uint32_t bb = bL + (uint32_t)(s * BN * LDS2 * 2) + kh * 32;
            ldsm4(fb[0][0], fb[0][1], fb[0][2], fb[0][3], bb);
            ldsm4(fb[1][0], fb[1][1], fb[1][2], fb[1][3], bb + 16 * LDS2 * 2);
        };

        float ac[2][4][4];
#pragma unroll
        for (int i = 0; i < 2; i++)
#pragma unroll
            for (int j = 0; j < 4; j++)
#pragma unroll
                for (int k = 0; k < 4; k++) ac[i][j][k] = 0.f;

        unsigned fa[2][2][4], fb[2][2][4];

        if (t == 0) {
            issue_A(0, 0); issue_B(0, 0); asm volatile("cp.async.commit_group;");
            issue_A(1, 1); issue_B(1, 1); asm volatile("cp.async.commit_group;");
            issue_A(2, 2); issue_B(2, 2); asm volatile("cp.async.commit_group;");
        } else {
            issue_A(0, 0); asm volatile("cp.async.commit_group;");
            issue_A(1, 1); asm volatile("cp.async.commit_group;");
            issue_A(2, 2); asm volatile("cp.async.commit_group;");
        }
        asm volatile("cp.async.wait_group %0;" :: "n"(ST2 - 2));
        __syncthreads();
        load_frag(0, 0, fa[0], fb[0]);
        int cur = 0;

        for (int kt = 0; kt < KT; kt++) {
            const int s = kt % ST2;
#pragma unroll
            for (int kh = 0; kh < KH; kh++) {
                if (kh < KH - 1) {
                    load_frag(s, kh + 1, fa[cur ^ 1], fb[cur ^ 1]);
                } else {
                    const int nk = kt + ST2 - 1;
                    if (nk < KT) {
                        issue_A(nk, nk % ST2);
                        issue_B(nk, nk % ST2);
                    }
                    asm volatile("cp.async.commit_group;");
                    asm volatile("cp.async.wait_group %0;" :: "n"(ST2 - 2));
                    __syncthreads();
                    if (kt + 1 < KT)
                        load_frag((kt + 1) % ST2, 0, fa[cur ^ 1], fb[cur ^ 1]);
                }
                mma16816(ac[0][0], fa[cur][0], fb[cur][0][0], fb[cur][0][1]);
                mma16816(ac[0][1], fa[cur][0], fb[cur][0][2], fb[cur][0][3]);
                mma16816(ac[0][2], fa[cur][0], fb[cur][1][0], fb[cur][1][1]);
                mma16816(ac[0][3], fa[cur][0], fb[cur][1][2], fb[cur][1][3]);
                mma16816(ac[1][0], fa[cur][1], fb[cur][0][0], fb[cur][0][1]);
                mma16816(ac[1][1], fa[cur][1], fb[cur][0][2], fb[cur][0][3]);
                mma16816(ac[1][2], fa[cur][1], fb[cur][1][0], fb[cur][1][1]);
                mma16816(ac[1][3], fa[cur][1], fb[cur][1][2], fb[cur][1][3]);
                cur ^= 1;
            }
        }

        const int last = (t == T - 1);
        if (!last) {
            issue_B(0, 0);
            issue_B(1, 1);
            issue_B(2, 2);
        }

#pragma unroll
        for (int mi = 0; mi < 2; mi++)
#pragma unroll
            for (int ni = 0; ni < 4; ni++) {
                float c0 = ac[mi][ni][0], c1 = ac[mi][ni][1];
                float c2 = ac[mi][ni][2], c3 = ac[mi][ni][3];
                float p0 = __shfl_xor_sync(0xffffffffu, c0, 1);
                float p1 = __shfl_xor_sync(0xffffffffu, c1, 1);
                float p2 = __shfl_xor_sync(0xffffffffu, c2, 1);
                float p3 = __shfl_xor_sync(0xffffffffu, c3, 1);
                const int mloc = warpM + mi * 16 + r + (evenq ? 0 : 8);
                const int uloc = (warpN + ni * 8 + 2 * (q & ~1)) >> 2;
                float gi = evenq ? c0 : p2;
                float gf = evenq ? c1 : p3;
                float gg = evenq ? p0 : c2;
                float go = evenq ? p1 : c3;
                const float4 bb = ((const float4*)bias)[(nbase >> 2) + uloc];
                gi += bb.x; gf += bb.y; gg += bb.z; go += bb.w;
                const float i_ = sigm(gi), f_ = sigm(gf);
                const float g_ = tanhf(gg), o_ = sigm(go);
                const float cc = f_ * creg[mi][ni] + i_ * g_;
                creg[mi][ni] = cc;
                const float h = o_ * tanhf(cc);
                hstage[mloc * 24 + uloc] = __float2half(h);
                if (last) {
                    hT [(size_t)(mbase + mloc) * H_ + (nbase >> 2) + uloc] = h;
                    cst[(size_t)(mbase + mloc) * H_ + (nbase >> 2) + uloc] = cc;
                }
            }
        __syncthreads();

        {
            const int m2  = tid >> 1;
            const int off = (tid & 1) * 8;
            uint4 hv = *(uint4*)&hstage[m2 * 24 + off];
            __half2* hh = (__half2*)&hv;
            uint4 rv; __half2* rr = (__half2*)&rv;
            const __half2 z2 = __floats2half2_rn(0.f, 0.f);
#pragma unroll
            for (int j = 0; j < 4; j++) rr[j] = __hmax2(hh[j], z2);
            const int mg = mbase + m2;
            const int ub = (nbase >> 2) + off;
            *(uint4*)&Anext[(size_t)mg * 2048 + ub]        = rv;
            *(uint4*)&Anext[(size_t)mg * 2048 + 1024 + ub] = hv;
            *(uint4*)&hs[(size_t)mg * H_ + ub]             = hv;
        }

        if (!last) grid_sync_group(NBG, myg);
    }
}

// ================= aux mma.sync GEMM (z-merged + decoder/mass2 fused) =================
struct GemmArgs {
    const __half* A;
    const __half* Bw;
    const __half* Bw2;
    const __half* A2;
    int K;
    const float* bias;
    const float* bias2;
    float*  c_state;
    __half* a16;
    __half* a16b;
    float*  outf;
    int T;
    int dec_ny;
};

template<int EPI>
__global__ void __launch_bounds__(256) gemm_k(GemmArgs g) {
    extern __shared__ __half sm[];
    __half* sA = sm;
    __half* sB = sm + STAGES * BM * LDS;

    const int tid  = threadIdx.x;
    const int lane = tid & 31;
    const int wid  = tid >> 5;
    const int warpM = (wid & 3) * 32;
    const int warpN = (wid >> 2) * 32;
    const int zz   = blockIdx.z;
    const int K = g.K;

    int mbase = blockIdx.y * BM;
    int nbase = blockIdx.x * BN;
    const __half* Bw   = zz ? g.Bw2  : g.Bw;
    const float*  bias = zz ? g.bias2 : g.bias;
    const __half* Aptr = g.A;
    bool massm = false;
    if (EPI == EPI_DEC && blockIdx.y >= g.dec_ny) {
        massm = true;
        const int idx = (blockIdx.y - g.dec_ny) * 2 + blockIdx.x;
        nbase = (idx & 15) * BN;
        mbase = (idx >> 4) * BM;
        Aptr = g.A2;
        Bw   = g.Bw2;
        bias = g.bias2;
    }
    const __half* Ag = Aptr + (size_t)mbase * K;
    const __half* Bg = Bw   + (size_t)nbase * K;

    const uint32_t smA = smem_u32(sA);
    const uint32_t smB = smem_u32(sB);

    const int l7  = lane & 7;
    const int grp = lane >> 3;
    const uint32_t aL = smA + (uint32_t)(((warpM + (grp & 1) * 8 + l7) * LDS + (grp >> 1) * 8) * 2);
    const uint32_t bL = smB + (uint32_t)(((warpN + (grp >> 1) * 8 + l7) * LDS + (grp & 1) * 8) * 2);

    const int aRow = tid >> 1, aCh = (tid & 1) * 2;
    const int bRow = tid >> 2, bCh = tid & 3;

    auto issue_stage = [&](int kt, int s) {
        const int ko = kt * BK;
        uint32_t sa = smA + (uint32_t)(((s * BM + aRow) * LDS + aCh * 8) * 2);
        const __half* gp = Ag + (size_t)aRow * K + ko + aCh * 8;
        cp16(sa, gp);
        cp16(sa + 16, gp + 8);
        uint32_t sb = smB + (uint32_t)(((s * BN + bRow) * LDS + bCh * 8) * 2);
        cp16(sb, Bg + (size_t)bRow * K + ko + bCh * 8);
        asm volatile("cp.async.commit_group;");
    };

    float ac[2][4][4];
#pragma unroll
    for (int i = 0; i < 2; i++)
#pragma unroll
        for (int j = 0; j < 4; j++)
#pragma unroll
            for (int k = 0; k < 4; k++) ac[i][j][k] = 0.f;

    const int KT = K / BK;
#pragma unroll
    for (int s = 0; s < STAGES - 1; s++) issue_stage(s, s);

    for (int kt = 0; kt < KT; kt++) {
        asm volatile("cp.async.wait_group %0;" :: "n"(STAGES - 2));
        __syncthreads();
        const int nk = kt + STAGES - 1;
        if (nk < KT) issue_stage(nk, nk % STAGES);
        else asm volatile("cp.async.commit_group;");

        const int s = kt % STAGES;
#pragma unroll
        for (int kh = 0; kh < 2; kh++) {
            unsigned a0[4], a1[4], b0[4], b1[4];
            const uint32_t ab = aL + (uint32_t)(s * BM * LDS * 2) + kh * 32;
            ldsm4(a0[0], a0[1], a0[2], a0[3], ab);
            ldsm4(a1[0], a1[1], a1[2], a1[3], ab + 16 * LDS * 2);
            const uint32_t bb = bL + (uint32_t)(s * BN * LDS * 2) + kh * 32;
            ldsm4(b0[0], b0[1], b0[2], b0[3], bb);
            ldsm4(b1[0], b1[1], b1[2], b1[3], bb + 16 * LDS * 2);

            mma16816(ac[0][0], a0, b0[0], b0[1]);
            mma16816(ac[0][1], a0, b0[2], b0[3]);
            mma16816(ac[0][2], a0, b1[0], b1[1]);
            mma16816(ac[0][3], a0, b1[2], b1[3]);
            mma16816(ac[1][0], a1, b0[0], b0[1]);
            mma16816(ac[1][1], a1, b0[2], b0[3]);
            mma16816(ac[1][2], a1, b1[0], b1[1]);
            mma16816(ac[1][3], a1, b1[2], b1[3]);
        }
    }

    const int r = lane >> 2, q = lane & 3;
#pragma unroll
    for (int mi = 0; mi < 2; mi++)
#pragma unroll
        for (int ni = 0; ni < 4; ni++) {
            const int col  = nbase + warpN + ni * 8 + 2 * q;
            const int row0 = mbase + warpM + mi * 16 + r;
            const int row1 = row0 + 8;
            const float v00 = ac[mi][ni][0], v01 = ac[mi][ni][1];
            const float v10 = ac[mi][ni][2], v11 = ac[mi][ni][3];
            const float b0f = bias[col], b1f = bias[col + 1];
            if (EPI == EPI_LRELU16) {
                *(__half2*)&g.a16[row0 * H_ + col] =
                    __floats2half2_rn(lrelu(v00 + b0f), lrelu(v01 + b1f));
                *(__half2*)&g.a16[row1 * H_ + col] =
                    __floats2half2_rn(lrelu(v10 + b0f), lrelu(v11 + b1f));
            } else if (EPI == EPI_LRELU2) {
                __half* dst = zz ? g.a16b : g.a16;
                *(__half2*)&dst[row0 * H_ + col] =
                    __floats2half2_rn(lrelu(v00 + b0f), lrelu(v01 + b1f));
                *(__half2*)&dst[row1 * H_ + col] =
                    __floats2half2_rn(lrelu(v10 + b0f), lrelu(v11 + b1f));
            } else if (EPI == EPI_H0C0) {
                if (zz == 0) {
                    float a0f = lrelu(v00 + b0f), a1f = lrelu(v01 + b1f);
                    float a2f = lrelu(v10 + b0f), a3f = lrelu(v11 + b1f);
                    *(__half2*)&g.a16[row0 * 2048 + 1024 + col] = __floats2half2_rn(a0f, a1f);
                    *(__half2*)&g.a16[row1 * 2048 + 1024 + col] = __floats2half2_rn(a2f, a3f);
                } else {
                    *(float2*)&g.c_state[row0 * H_ + col] =
                        make_float2(lrelu(v00 + b0f), lrelu(v01 + b1f));
                    *(float2*)&g.c_state[row1 * H_ + col] =
                        make_float2(lrelu(v10 + b0f), lrelu(v11 + b1f));
                }
            } else { // EPI_DEC (fused with mass2)
                if (massm) {
                    *(__half2*)&g.a16[row0 * H_ + col] =
                        __floats2half2_rn(lrelu(v00 + b0f), lrelu(v01 + b1f));
                    *(__half2*)&g.a16[row1 * H_ + col] =
                        __floats2half2_rn(lrelu(v10 + b0f), lrelu(v11 + b1f));
                } else {
                    const int bb0 = row0 & 255, tt0 = row0 >> 8;
                    const int bb1 = row1 & 255, tt1 = row1 >> 8;
                    *(float2*)&g.outf[(size_t)bb0 * g.T * O_ + tt0 * O_ + col] =
                        make_float2(v00 + b0f, v01 + b1f);
                    *(float2*)&g.outf[(size_t)bb1 * g.T * O_ + tt1 * O_ + col] =
                        make_float2(v10 + b0f, v11 + b1f);
                }
            }
        }
}

// ================= fused setup: wcat + prep + bperm + x0a0 in ONE launch =================
#define WCAT_BLKS  4096                 // 4096*2048/8 chunks / 256 thr
#define PREP_N     (4*H_*LAT_ + H_*H_ + O_*H_ + 2*B_*LAT_)   // 3538944
#define PREP_BLKS  (PREP_N / 1024)      // 3456 (4 elems/thread)
#define BPERM_BLKS 16
#define X0_BLKS    4
#define SETUP_BLKS (WCAT_BLKS + PREP_BLKS + BPERM_BLKS + X0_BLKS)

__device__ __forceinline__ void cvt4(__half* dst, const float* src) {
    float4 f = *(const float4*)src;
    __half2 h[2] = { __floats2half2_rn(f.x, f.y), __floats2half2_rn(f.z, f.w) };
    *(uint2*)dst = *(uint2*)h;
}

__global__ void setup_all(const float* __restrict__ W_ih, const float* __restrict__ W_hh,
                          const float* __restrict__ b_ih, const float* __restrict__ b_hh,
                          const float* __restrict__ l2h,  const float* __restrict__ l2h2,
                          const float* __restrict__ seqw, const float* __restrict__ massw,
                          const float* __restrict__ mass2w, const float* __restrict__ outw,
                          const float* __restrict__ ench_f, const float* __restrict__ enco_f,
                          const float* __restrict__ st, const float* __restrict__ embw,
                          const float* __restrict__ embb) {
    const int b   = blockIdx.x;
    const int tid = threadIdx.x;
    if (b < WCAT_BLKS) {
        // g_Wcat permute, 8 halfs per thread
        const int idx8 = b * 256 + tid;
        const int np = idx8 >> 8;
        const int kc = (idx8 & 255) << 3;
        const int j = np >> 2, gg = np & 3;
        const int srow = gg * 1024 + j;
        const float* src = (kc < 1024) ? (W_ih + (size_t)srow * 1024 + kc)
                                       : (W_hh + (size_t)srow * 1024 + kc - 1024);
        float4 f0 = ((const float4*)src)[0];
        float4 f1 = ((const float4*)src)[1];
        __half2 h[4] = { __floats2half2_rn(f0.x, f0.y), __floats2half2_rn(f0.z, f0.w),
                         __floats2half2_rn(f1.x, f1.y), __floats2half2_rn(f1.z, f1.w) };
        *(uint4*)&g_Wcat[(size_t)np * 2048 + kc] = *(uint4*)h;
    } else if (b < WCAT_BLKS + PREP_BLKS) {
        // weight/input conversions, 4 elems per thread
        const int i = ((b - WCAT_BLKS) * 256 + tid) * 4;
        const int S = H_ * LAT_;
        if (i < S)                    cvt4(&g_w_l2h [i],          l2h    + i);
        else if (i < 2 * S)           cvt4(&g_w_l2h2[i - S],      l2h2   + (i - S));
        else if (i < 3 * S)           cvt4(&g_w_seq [i - 2 * S],  seqw   + (i - 2 * S));
        else if (i < 4 * S)           cvt4(&g_w_mass[i - 3 * S],  massw  + (i - 3 * S));
        else if (i < 4 * S + H_ * H_) cvt4(&g_w_mass2[i - 4 * S], mass2w + (i - 4 * S));
        else {
            const int jj = i - 4 * S - H_ * H_;
            if (jj < O_ * H_)                    cvt4(&g_w_out[jj], outw + jj);
            else if (jj < O_ * H_ + B_ * LAT_)   cvt4(&g_enc_h[jj - O_ * H_],
                                                      ench_f + (jj - O_ * H_));
            else                                 cvt4(&g_enc_o[jj - O_ * H_ - B_ * LAT_],
                                                      enco_f + (jj - O_ * H_ - B_ * LAT_));
        }
    } else if (b < WCAT_BLKS + PREP_BLKS + BPERM_BLKS) {
        const int idx = (b - WCAT_BLKS - PREP_BLKS) * 256 + tid;   // < 4096
        const int jj = idx >> 2, g2 = idx & 3;
        g_bperm[idx] = b_ih[g2 * 1024 + jj] + b_hh[g2 * 1024 + jj];
    } else {
        // x0a0: u = block-local, relu(emb(start)) broadcast over batch
        const int u = (b - WCAT_BLKS - PREP_BLKS - BPERM_BLKS) * 256 + tid;
        float s = embb[u];
#pragma unroll 4
        for (int k = 0; k < O_; k++) s += st[k] * embw[u * O_ + k];
        __half rr = __float2half(fmaxf(s, 0.f));
        for (int m = 0; m < B_; m++) g_A[0][m * 2048 + u] = rr;
    }
}

__global__ void heads_kernel(const float* __restrict__ w2, const float* __restrict__ b2,
                             const float* __restrict__ w3, const float* __restrict__ b3,
                             float* __restrict__ num, float* __restrict__ mass) {
    int m = blockIdx.x * (blockDim.x >> 5) + (threadIdx.x >> 5);
    int lane = threadIdx.x & 31;
    float d0 = 0.f, d1 = 0.f, d2 = 0.f;
    for (int k = lane; k < H_; k += 32) {
        float s = __half2float(g_s1[m * H_ + k]);
        float t = __half2float(g_m2[m * H_ + k]);
        d0 += s * w2[k];
        d1 += t * w3[k];
        d2 += t * w3[H_ + k];
    }
#pragma unroll
    for (int o = 16; o; o >>= 1) {
        d0 += __shfl_down_sync(0xffffffffu, d0, o);
        d1 += __shfl_down_sync(0xffffffffu, d1, o);
        d2 += __shfl_down_sync(0xffffffffu, d2, o);
    }
    if (lane == 0) {
        num[m] = fmaxf(d0 + b2[0], 0.f);
        float e0 = d1 + b3[0], e1 = d2 + b3[1];
        float mx = fmaxf(e0, e1);
        float p0 = expf(e0 - mx), p1 = expf(e1 - mx);
        float inv = 1.f / (p0 + p1);
        mass[m * 2 + 0] = p0 * inv;
        mass[m * 2 + 1] = p1 * inv;
    }
}

// ================= host launcher =================
extern "C" void kernel_launch(void* const* d_in, const int* in_sizes, int n_in,
                              void* d_out, int out_size) {
    const float* enc_out     = (const float*)d_in[0];
    const float* enc_hid     = (const float*)d_in[1];
    const float* start_token = (const float*)d_in[2];
    const float* lat2hid_w   = (const float*)d_in[3];
    const float* lat2hid_b   = (const float*)d_in[4];
    const float* lat2hid2_w  = (const float*)d_in[5];
    const float* lat2hid2_b  = (const float*)d_in[6];
    const float* emb_fc_w    = (const float*)d_in[7];
    const float* emb_fc_b    = (const float*)d_in[8];
    const float* W_ih        = (const float*)d_in[9];
    const float* W_hh        = (const float*)d_in[10];
    const float* b_ih        = (const float*)d_in[11];
    const float* b_hh        = (const float*)d_in[12];
    const float* out_w       = (const float*)d_in[13];
    const float* out_b       = (const float*)d_in[14];
    const float* fc_seq_w    = (const float*)d_in[15];
    const float* fc_seq_b    = (const float*)d_in[16];
    const float* fc_seq2_w   = (const float*)d_in[17];
    const float* fc_seq2_b   = (const float*)d_in[18];
    const float* fc_mass_w   = (const float*)d_in[19];
    const float* fc_mass_b   = (const float*)d_in[20];
    const float* fc_mass2_w  = (const float*)d_in[21];
    const float* fc_mass2_b  = (const float*)d_in[22];
    const float* fc_mass3_w  = (const float*)d_in[23];
    const float* fc_mass3_b  = (const float*)d_in[24];

    int T = (out_size - 2 * B_ * H_ - B_ - B_ * NPART_) / (B_ * O_);
    if (T < 1) T = 1;
    if (T > MAXT) T = MAXT;

    float* out  = (float*)d_out;
    float* dec  = out;
    float* hT   = out + (size_t)B_ * T * O_;
    float* cT   = hT + B_ * H_;
    float* num  = cT + B_ * H_;
    float* mass = num + B_;

    void* p;
    cudaGetSymbolAddress(&p, g_bperm);   float*  bperm = (float*)p;
    cudaGetSymbolAddress(&p, g_A);       __half* Abuf  = (__half*)p;
    cudaGetSymbolAddress(&p, g_hs);      __half* hsb   = (__half*)p;
    cudaGetSymbolAddress(&p, g_w_l2h);   __half* wl2h  = (__half*)p;
    cudaGetSymbolAddress(&p, g_w_l2h2);  __half* wl2h2 = (__half*)p;
    cudaGetSymbolAddress(&p, g_w_seq);   __half* wseq  = (__half*)p;
    cudaGetSymbolAddress(&p, g_w_mass);  __half* wmass = (__half*)p;
    cudaGetSymbolAddress(&p, g_w_mass2); __half* wmass2= (__half*)p;
    cudaGetSymbolAddress(&p, g_w_out);   __half* wout  = (__half*)p;
    cudaGetSymbolAddress(&p, g_enc_h);   __half* ench  = (__half*)p;
    cudaGetSymbolAddress(&p, g_enc_o);   __half* enco  = (__half*)p;
    cudaGetSymbolAddress(&p, g_s1);      __half* s1    = (__half*)p;
    cudaGetSymbolAddress(&p, g_m1);      __half* m1    = (__half*)p;
    cudaGetSymbolAddress(&p, g_m2);      __half* m2    = (__half*)p;

    cudaFuncSetAttribute(gemm_k<EPI_H0C0>,   cudaFuncAttributeMaxDynamicSharedMemorySize, SMEM_BYTES);
    cudaFuncSetAttribute(gemm_k<EPI_LRELU2>, cudaFuncAttributeMaxDynamicSharedMemorySize, SMEM_BYTES);
    cudaFuncSetAttribute(gemm_k<EPI_DEC>,    cudaFuncAttributeMaxDynamicSharedMemorySize, SMEM_BYTES);
    cudaFuncSetAttribute(lstm_persist,       cudaFuncAttributeMaxDynamicSharedMemorySize, PSMEM);

    // 0: ALL setup in one launch (wcat permute + conversions + bperm + x0a0)
    setup_all<<<SETUP_BLKS, 256>>>(W_ih, W_hh, b_ih, b_hh,
                                   lat2hid_w, lat2hid2_w, fc_seq_w, fc_mass_w,
                                   fc_mass2_w, out_w, enc_hid, enc_out,
                                   start_token, emb_fc_w, emb_fc_b);

    GemmArgs ga;
    // 1: h0 (z=0 -> A0[:,1024:2048]) + c0 (z=1 -> cT) in ONE launch
    ga = GemmArgs{}; ga.T = T;
    ga.A = ench; ga.Bw = wl2h; ga.Bw2 = wl2h2; ga.K = LAT_;
    ga.bias = lat2hid_b; ga.bias2 = lat2hid2_b;
    ga.a16 = Abuf; ga.c_state = cT;
    gemm_k<EPI_H0C0><<<dim3(H_ / BN, B_ / BM, 2), 256, SMEM_BYTES>>>(ga);

    // 2: persistent LSTM — all T steps, one launch
    lstm_persist<<<dim3(4096 / BN, B_ / BM), 256, PSMEM>>>(bperm, cT, hT, hsb, T);

    // 3: heads: fc_seq (z=0 -> s1) + fc_mass (z=1 -> m1)
    ga = GemmArgs{}; ga.T = T;
    ga.A = enco; ga.Bw = wseq; ga.Bw2 = wmass; ga.K = LAT_;
    ga.bias = fc_seq_b; ga.bias2 = fc_mass_b;
    ga.a16 = s1; ga.a16b = m1;
    gemm_k<EPI_LRELU2><<<dim3(H_ / BN, B_ / BM, 2), 256, SMEM_BYTES>>>(ga);

    // 4: decoder projection FUSED with fc_mass2
    {
        const int dec_ny = (T * B_) / BM;
        const int mass_ny = 16;
        ga = GemmArgs{}; ga.T = T;
        ga.A = hsb; ga.Bw = wout; ga.K = H_; ga.bias = out_b; ga.outf = dec;
        ga.A2 = m1; ga.Bw2 = wmass2; ga.bias2 = fc_mass2_b; ga.a16 = m2;
        ga.dec_ny = dec_ny;
        gemm_k<EPI_DEC><<<dim3(O_ / BN, dec_ny + mass_ny), 256, SMEM_BYTES>>>(ga);
    }

    // 5: scalar heads
    heads_kernel<<<32, 256>>>(fc_seq2_w, fc_seq2_b, fc_mass3_w, fc_mass3_b, num, mass);
}

// round 16
// speedup vs baseline: 1.5134x; 1.5134x over previous
#include <cuda_runtime.h>
#include <cuda_fp16.h>
#include <math.h>
#include <stdint.h>

#define B_    256
#define LAT_  512
#define H_    1024
#define O_    128
#define NPART_ 2
#define MAXT  128

// ---- aux mma.sync GEMM config ----
#define BM 128
#define BN 64
#define BK 32
#define STAGES 4
#define LDS 40
#define SMEM_BYTES (STAGES*(BM+BN)*LDS*2)
enum { EPI_LRELU16 = 0, EPI_H0C0, EPI_LRELU2, EPI_DEC };

// ---- persistent LSTM mainloop config (256 threads, 8 warps, 4 stages) ----
#define BK2   64
#define KH    4
#define ST2   4
#define LDS2  72
#define PSMEM (ST2*(BM+BN)*LDS2*2)   // 110592 B

// ---- device scratch ----
__device__ __align__(16) __half g_Wcat[4096u*2048u];
__device__ __align__(16) float  g_bperm[4096];
__device__ __align__(16) __half g_A[2][B_*2048];
__device__ __align__(16) __half g_hs[(size_t)MAXT*B_*H_];
__device__ __align__(16) __half g_w_l2h [H_*LAT_];
__device__ __align__(16) __half g_w_l2h2[H_*LAT_];
__device__ __align__(16) __half g_w_seq [H_*LAT_];
__device__ __align__(16) __half g_w_mass[H_*LAT_];
__device__ __align__(16) __half g_w_mass2[H_*H_];
__device__ __align__(16) __half g_w_out [O_*H_];
__device__ __align__(16) __half g_enc_h[B_*LAT_];
__device__ __align__(16) __half g_enc_o[B_*LAT_];
__device__ __align__(16) __half g_s1[B_*H_];
__device__ __align__(16) __half g_m1[B_*H_];
__device__ __align__(16) __half g_m2[B_*H_];

// per-my-group barrier state, 128B-separated
__device__ __align__(128) unsigned g_barc2[64];
__device__ __align__(128) unsigned g_barg2[64];

// ---- helpers ----
__device__ __forceinline__ uint32_t smem_u32(const void* p) {
    return (uint32_t)__cvta_generic_to_shared(p);
}
__device__ __forceinline__ void cp16(uint32_t s, const void* g) {
    asm volatile("cp.async.cg.shared.global [%0], [%1], 16;" :: "r"(s), "l"(g));
}
__device__ __forceinline__ void ldsm4(unsigned &r0, unsigned &r1, unsigned &r2, unsigned &r3,
                                      uint32_t addr) {
    asm volatile("ldmatrix.sync.aligned.m8n8.x4.shared.b16 {%0,%1,%2,%3}, [%4];"
                 : "=r"(r0), "=r"(r1), "=r"(r2), "=r"(r3) : "r"(addr));
}
__device__ __forceinline__ void mma16816(float* c, const unsigned* a, unsigned b0, unsigned b1) {
    asm volatile("mma.sync.aligned.m16n8k16.row.col.f32.f16.f16.f32 "
                 "{%0,%1,%2,%3}, {%4,%5,%6,%7}, {%8,%9}, {%0,%1,%2,%3};"
                 : "+f"(c[0]), "+f"(c[1]), "+f"(c[2]), "+f"(c[3])
                 : "r"(a[0]), "r"(a[1]), "r"(a[2]), "r"(a[3]), "r"(b0), "r"(b1));
}
__device__ __forceinline__ float lrelu(float x) { return x > 0.f ? x : 0.01f * x; }
__device__ __forceinline__ float sigm(float x) { return 1.f / (1.f + __expf(-x)); }

// per-group barrier: only the 64 CTAs sharing blockIdx.y must sync
__device__ __forceinline__ void grid_sync_group(unsigned nb, int grp) {
    unsigned* cc = &g_barc2[grp * 32];
    unsigned* gg = &g_barg2[grp * 32];
    __syncthreads();
    if (threadIdx.x == 0) {
        __threadfence();
        unsigned target;
        asm volatile("ld.volatile.global.u32 %0, [%1];" : "=r"(target) : "l"(gg));
        unsigned old = atomicAdd(cc, 1u);
        if (old == nb - 1u) {
            *cc = 0u;
            __threadfence();
            atomicAdd(gg, 1u);
        } else {
            unsigned cur;
            do {
                asm volatile("ld.volatile.global.u32 %0, [%1];" : "=r"(cur) : "l"(gg));
            } while ((int)(cur - target) <= 0);
        }
        __threadfence();
    }
    __syncthreads();
}

// ================= persistent LSTM (exact round-8 schedule, split barrier) =================
__global__ void __launch_bounds__(256, 1)
lstm_persist(const float* __restrict__ bias, float* __restrict__ cst,
             float* __restrict__ hT, __half* __restrict__ hs_all, int T) {
    extern __shared__ __half sm[];
    __half* sA = sm;                        // ST2 * BM * LDS2
    __half* sB = sm + ST2 * BM * LDS2;      // ST2 * BN * LDS2
    __half* hstage = sm;                    // 128 x 24 halfs, reuses sA after mainloop

    const int tid  = threadIdx.x;
    const int lane = tid & 31;
    const int wid  = tid >> 5;
    const int warpM = (wid & 3) * 32;
    const int warpN = (wid >> 2) * 32;
    const int mbase = blockIdx.y * BM;
    const int nbase = blockIdx.x * BN;
    const __half* Bg = g_Wcat + (size_t)nbase * 2048;

    const uint32_t smA = smem_u32(sA);
    const uint32_t smB = smem_u32(sB);
    const int l7  = lane & 7;
    const int grp = lane >> 3;
    const uint32_t aL = smA + (uint32_t)(((warpM + (grp & 1) * 8 + l7) * LDS2 + (grp >> 1) * 8) * 2);
    const uint32_t bL = smB + (uint32_t)(((warpN + (grp >> 1) * 8 + l7) * LDS2 + (grp & 1) * 8) * 2);
    const int r = lane >> 2, q = lane & 3;
    const unsigned NBG = gridDim.x;
    const int myg = blockIdx.y;
    const int KT = 2048 / BK2;              // 32
    const bool evenq = !(q & 1);

    float creg[2][4];
#pragma unroll
    for (int mi = 0; mi < 2; mi++)
#pragma unroll
        for (int ni = 0; ni < 4; ni++) {
            const int m = mbase + warpM + mi * 16 + r + (evenq ? 0 : 8);
            const int u = (nbase + warpN + ni * 8 + 2 * (q & ~1)) >> 2;
            creg[mi][ni] = cst[(size_t)m * H_ + u];
        }

    auto issue_B = [&](int kt, int s) {
        const int ko = kt * BK2;
#pragma unroll
        for (int j = 0; j < 2; j++) {
            const int c = tid + j * 256;
            const int row = c >> 3, ch = c & 7;
            cp16(smB + (uint32_t)(((s * BN + row) * LDS2 + ch * 8) * 2),
                 Bg + (size_t)row * 2048 + ko + ch * 8);
        }
    };

    for (int t = 0; t < T; t++) {
        const __half* Ag = g_A[t & 1] + (size_t)mbase * 2048;
        __half* Anext = g_A[(t + 1) & 1];
        __half* hs = hs_all + (size_t)t * B_ * H_;

        auto issue_A = [&](int kt, int s) {
            const int ko = kt * BK2;
#pragma unroll
            for (int j = 0; j < 4; j++) {
                const int c = tid + j * 256;
                const int row = c >> 3, ch = c & 7;
                cp16(smA + (uint32_t)(((s * BM + row) * LDS2 + ch * 8) * 2),
                     Ag + (size_t)row * 2048 + ko + ch * 8);
            }
        };

        auto load_frag = [&](int s, int kh, unsigned (&fa)[2][4], unsigned (&fb)[2][4]) {
            const uint32_t ab = aL + (uint32_t)(s * BM * LDS2 * 2) + kh * 32;
            ldsm4(fa[0][0], fa[0][1], fa[0][2], fa[0][3], ab);
            ldsm4(fa[1][0], fa[1][1], fa[1][2], fa[1][3], ab + 16 * LDS2 * 2);
            const uint32_t bb = bL + (uint32_t)(s * BN * LDS2 * 2) + kh * 32;
            ldsm4(fb[0][0], fb[0][1], fb[0][2], fb[0][3], bb);
            ldsm4(fb[1][0], fb[1][1], fb[1][2], fb[1][3], bb + 16 * LDS2 * 2);
        };

        float ac[2][4][4];
#pragma unroll
        for (int i = 0; i < 2; i++)
#pragma unroll
            for (int j = 0; j < 4; j++)
#pragma unroll
                for (int k = 0; k < 4; k++) ac[i][j][k] = 0.f;

        unsigned fa[2][2][4], fb[2][2][4];

        if (t == 0) {
            issue_A(0, 0); issue_B(0, 0); asm volatile("cp.async.commit_group;");
            issue_A(1, 1); issue_B(1, 1); asm volatile("cp.async.commit_group;");
            issue_A(2, 2); issue_B(2, 2); asm volatile("cp.async.commit_group;");
        } else {
            issue_A(0, 0); asm volatile("cp.async.commit_group;");
            issue_A(1, 1); asm volatile("cp.async.commit_group;");
            issue_A(2, 2); asm volatile("cp.async.commit_group;");
        }
        asm volatile("cp.async.wait_group %0;" :: "n"(ST2 - 2));
        __syncthreads();
        load_frag(0, 0, fa[0], fb[0]);
        int cur = 0;

        for (int kt = 0; kt < KT; kt++) {
            const int s = kt % ST2;
#pragma unroll
            for (int kh = 0; kh < KH; kh++) {
                if (kh < KH - 1) {
                    load_frag(s, kh + 1, fa[cur ^ 1], fb[cur ^ 1]);
                } else {
                    const int nk = kt + ST2 - 1;
                    if (nk < KT) {
                        issue_A(nk, nk % ST2);
                        issue_B(nk, nk % ST2);
                    }
                    asm volatile("cp.async.commit_group;");
                    asm volatile("cp.async.wait_group %0;" :: "n"(ST2 - 2));
                    __syncthreads();
                    if (kt + 1 < KT)
                        load_frag((kt + 1) % ST2, 0, fa[cur ^ 1], fb[cur ^ 1]);
                }
                mma16816(ac[0][0], fa[cur][0], fb[cur][0][0], fb[cur][0][1]);
                mma16816(ac[0][1], fa[cur][0], fb[cur][0][2], fb[cur][0][3]);
                mma16816(ac[0][2], fa[cur][0], fb[cur][1][0], fb[cur][1][1]);
                mma16816(ac[0][3], fa[cur][0], fb[cur][1][2], fb[cur][1][3]);
                mma16816(ac[1][0], fa[cur][1], fb[cur][0][0], fb[cur][0][1]);
                mma16816(ac[1][1], fa[cur][1], fb[cur][0][2], fb[cur][0][3]);
                mma16816(ac[1][2], fa[cur][1], fb[cur][1][0], fb[cur][1][1]);
                mma16816(ac[1][3], fa[cur][1], fb[cur][1][2], fb[cur][1][3]);
                cur ^= 1;
            }
        }

        const int last = (t == T - 1);
        if (!last) {
            issue_B(0, 0);
            issue_B(1, 1);
            issue_B(2, 2);
        }

#pragma unroll
        for (int mi = 0; mi < 2; mi++)
#pragma unroll
            for (int ni = 0; ni < 4; ni++) {
                float c0 = ac[mi][ni][0], c1 = ac[mi][ni][1];
                float c2 = ac[mi][ni][2], c3 = ac[mi][ni][3];
                float p0 = __shfl_xor_sync(0xffffffffu, c0, 1);
                float p1 = __shfl_xor_sync(0xffffffffu, c1, 1);
                float p2 = __shfl_xor_sync(0xffffffffu, c2, 1);
                float p3 = __shfl_xor_sync(0xffffffffu, c3, 1);
                const int mloc = warpM + mi * 16 + r + (evenq ? 0 : 8);
                const int uloc = (warpN + ni * 8 + 2 * (q & ~1)) >> 2;
                float gi = evenq ? c0 : p2;
                float gf = evenq ? c1 : p3;
                float gg = evenq ? p0 : c2;
                float go = evenq ? p1 : c3;
                const float4 bb = ((const float4*)bias)[(nbase >> 2) + uloc];
                gi += bb.x; gf += bb.y; gg += bb.z; go += bb.w;
                const float i_ = sigm(gi), f_ = sigm(gf);
                const float g_ = tanhf(gg), o_ = sigm(go);
                const float cc = f_ * creg[mi][ni] + i_ * g_;
                creg[mi][ni] = cc;
                const float h = o_ * tanhf(cc);
                hstage[mloc * 24 + uloc] = __float2half(h);
                if (last) {
                    hT [(size_t)(mbase + mloc) * H_ + (nbase >> 2) + uloc] = h;
                    cst[(size_t)(mbase + mloc) * H_ + (nbase >> 2) + uloc] = cc;
                }
            }
        __syncthreads();

        {
            const int m2  = tid >> 1;
            const int off = (tid & 1) * 8;
            uint4 hv = *(uint4*)&hstage[m2 * 24 + off];
            __half2* hh = (__half2*)&hv;
            uint4 rv; __half2* rr = (__half2*)&rv;
            const __half2 z2 = __floats2half2_rn(0.f, 0.f);
#pragma unroll
            for (int j = 0; j < 4; j++) rr[j] = __hmax2(hh[j], z2);
            const int mg = mbase + m2;
            const int ub = (nbase >> 2) + off;
            *(uint4*)&Anext[(size_t)mg * 2048 + ub]        = rv;
            *(uint4*)&Anext[(size_t)mg * 2048 + 1024 + ub] = hv;
            *(uint4*)&hs[(size_t)mg * H_ + ub]             = hv;
        }

        if (!last) grid_sync_group(NBG, myg);
    }
}

// ================= aux mma.sync GEMM (z-merged + decoder/mass2 fused) =================
struct GemmArgs {
    const __half* A;
    const __half* Bw;
    const __half* Bw2;
    const __half* A2;
    int K;
    const float* bias;
    const float* bias2;
    float*  c_state;
    __half* a16;
    __half* a16b;
    float*  outf;
    int T;
    int dec_ny;
};

template<int EPI>
__global__ void __launch_bounds__(256) gemm_k(GemmArgs g) {
    extern __shared__ __half sm[];
    __half* sA = sm;
    __half* sB = sm + STAGES * BM * LDS;

    const int tid  = threadIdx.x;
    const int lane = tid & 31;
    const int wid  = tid >> 5;
    const int warpM = (wid & 3) * 32;
    const int warpN = (wid >> 2) * 32;
    const int zz   = blockIdx.z;
    const int K = g.K;

    int mbase = blockIdx.y * BM;
    int nbase = blockIdx.x * BN;
    const __half* Bw   = zz ? g.Bw2  : g.Bw;
    const float*  bias = zz ? g.bias2 : g.bias;
    const __half* Aptr = g.A;
    bool massm = false;
    if (EPI == EPI_DEC && blockIdx.y >= g.dec_ny) {
        massm = true;
        const int idx = (blockIdx.y - g.dec_ny) * 2 + blockIdx.x;
        nbase = (idx & 15) * BN;
        mbase = (idx >> 4) * BM;
        Aptr = g.A2;
        Bw   = g.Bw2;
        bias = g.bias2;
    }
    const __half* Ag = Aptr + (size_t)mbase * K;
    const __half* Bg = Bw   + (size_t)nbase * K;

    const uint32_t smA = smem_u32(sA);
    const uint32_t smB = smem_u32(sB);

    const int l7  = lane & 7;
    const int grp = lane >> 3;
    const uint32_t aL = smA + (uint32_t)(((warpM + (grp & 1) * 8 + l7) * LDS + (grp >> 1) * 8) * 2);
    const uint32_t bL = smB + (uint32_t)(((warpN + (grp >> 1) * 8 + l7) * LDS + (grp & 1) * 8) * 2);

    const int aRow = tid >> 1, aCh = (tid & 1) * 2;
    const int bRow = tid >> 2, bCh = tid & 3;

    auto issue_stage = [&](int kt, int s) {
        const int ko = kt * BK;
        uint32_t sa = smA + (uint32_t)(((s * BM + aRow) * LDS + aCh * 8) * 2);
        const __half* gp = Ag + (size_t)aRow * K + ko + aCh * 8;
        cp16(sa, gp);
        cp16(sa + 16, gp + 8);
        uint32_t sb = smB + (uint32_t)(((s * BN + bRow) * LDS + bCh * 8) * 2);
        cp16(sb, Bg + (size_t)bRow * K + ko + bCh * 8);
        asm volatile("cp.async.commit_group;");
    };

    float ac[2][4][4];
#pragma unroll
    for (int i = 0; i < 2; i++)
#pragma unroll
        for (int j = 0; j < 4; j++)
#pragma unroll
            for (int k = 0; k < 4; k++) ac[i][j][k] = 0.f;

    const int KT = K / BK;
#pragma unroll
    for (int s = 0; s < STAGES - 1; s++) issue_stage(s, s);

    for (int kt = 0; kt < KT; kt++) {
        asm volatile("cp.async.wait_group %0;" :: "n"(STAGES - 2));
        __syncthreads();
        const int nk = kt + STAGES - 1;
        if (nk < KT) issue_stage(nk, nk % STAGES);
        else asm volatile("cp.async.commit_group;");

        const int s = kt % STAGES;
#pragma unroll
        for (int kh = 0; kh < 2; kh++) {
            unsigned a0[4], a1[4], b0[4], b1[4];
            const uint32_t ab = aL + (uint32_t)(s * BM * LDS * 2) + kh * 32;
            ldsm4(a0[0], a0[1], a0[2], a0[3], ab);
            ldsm4(a1[0], a1[1], a1[2], a1[3], ab + 16 * LDS * 2);
            const uint32_t bb = bL + (uint32_t)(s * BN * LDS * 2) + kh * 32;
            ldsm4(b0[0], b0[1], b0[2], b0[3], bb);
            ldsm4(b1[0], b1[1], b1[2], b1[3], bb + 16 * LDS * 2);

            mma16816(ac[0][0], a0, b0[0], b0[1]);
            mma16816(ac[0][1], a0, b0[2], b0[3]);
            mma16816(ac[0][2], a0, b1[0], b1[1]);
            mma16816(ac[0][3], a0, b1[2], b1[3]);
            mma16816(ac[1][0], a1, b0[0], b0[1]);
            mma16816(ac[1][1], a1, b0[2], b0[3]);
            mma16816(ac[1][2], a1, b1[0], b1[1]);
            mma16816(ac[1][3], a1, b1[2], b1[3]);
        }
    }

    const int r = lane >> 2, q = lane & 3;
#pragma unroll
    for (int mi = 0; mi < 2; mi++)
#pragma unroll
        for (int ni = 0; ni < 4; ni++) {
            const int col  = nbase + warpN + ni * 8 + 2 * q;
            const int row0 = mbase + warpM + mi * 16 + r;
            const int row1 = row0 + 8;
            const float v00 = ac[mi][ni][0], v01 = ac[mi][ni][1];
            const float v10 = ac[mi][ni][2], v11 = ac[mi][ni][3];
            const float b0f = bias[col], b1f = bias[col + 1];
            if (EPI == EPI_LRELU16) {
                *(__half2*)&g.a16[row0 * H_ + col] =
                    __floats2half2_rn(lrelu(v00 + b0f), lrelu(v01 + b1f));
                *(__half2*)&g.a16[row1 * H_ + col] =
                    __floats2half2_rn(lrelu(v10 + b0f), lrelu(v11 + b1f));
            } else if (EPI == EPI_LRELU2) {
                __half* dst = zz ? g.a16b : g.a16;
                *(__half2*)&dst[row0 * H_ + col] =
                    __floats2half2_rn(lrelu(v00 + b0f), lrelu(v01 + b1f));
                *(__half2*)&dst[row1 * H_ + col] =
                    __floats2half2_rn(lrelu(v10 + b0f), lrelu(v11 + b1f));
            } else if (EPI == EPI_H0C0) {
                if (zz == 0) {
                    float a0f = lrelu(v00 + b0f), a1f = lrelu(v01 + b1f);
                    float a2f = lrelu(v10 + b0f), a3f = lrelu(v11 + b1f);
                    *(__half2*)&g.a16[row0 * 2048 + 1024 + col] = __floats2half2_rn(a0f, a1f);
                    *(__half2*)&g.a16[row1 * 2048 + 1024 + col] = __floats2half2_rn(a2f, a3f);
                } else {
                    *(float2*)&g.c_state[row0 * H_ + col] =
                        make_float2(lrelu(v00 + b0f), lrelu(v01 + b1f));
                    *(float2*)&g.c_state[row1 * H_ + col] =
                        make_float2(lrelu(v10 + b0f), lrelu(v11 + b1f));
                }
            } else { // EPI_DEC (fused with mass2)
                if (massm) {
                    *(__half2*)&g.a16[row0 * H_ + col] =
                        __floats2half2_rn(lrelu(v00 + b0f), lrelu(v01 + b1f));
                    *(__half2*)&g.a16[row1 * H_ + col] =
                        __floats2half2_rn(lrelu(v10 + b0f), lrelu(v11 + b1f));
                } else {
                    const int bb0 = row0 & 255, tt0 = row0 >> 8;
                    const int bb1 = row1 & 255, tt1 = row1 >> 8;
                    *(float2*)&g.outf[(size_t)bb0 * g.T * O_ + tt0 * O_ + col] =
                        make_float2(v00 + b0f, v01 + b1f);
                    *(float2*)&g.outf[(size_t)bb1 * g.T * O_ + tt1 * O_ + col] =
                        make_float2(v10 + b0f, v11 + b1f);
                }
            }
        }
}

// ================= setup kernels (round-13 structure, vectorized bodies) =================
#define PREP_N (4*H_*LAT_ + H_*H_ + O_*H_ + 2*B_*LAT_)

__device__ __forceinline__ void cvt4(__half* dst, const float* src) {
    float4 f = *(const float4*)src;
    __half2 h[2] = { __floats2half2_rn(f.x, f.y), __floats2half2_rn(f.z, f.w) };
    *(uint2*)dst = *(uint2*)h;
}

__global__ void prep_kernel(const float* __restrict__ l2h,  const float* __restrict__ l2h2,
                            const float* __restrict__ seqw, const float* __restrict__ massw,
                            const float* __restrict__ mass2w, const float* __restrict__ outw,
                            const float* __restrict__ ench_f, const float* __restrict__ enco_f) {
    const int i = (blockIdx.x * blockDim.x + threadIdx.x) * 4;
    const int S = H_ * LAT_;
    if (i < S)                    cvt4(&g_w_l2h [i],          l2h    + i);
    else if (i < 2 * S)           cvt4(&g_w_l2h2[i - S],      l2h2   + (i - S));
    else if (i < 3 * S)           cvt4(&g_w_seq [i - 2 * S],  seqw   + (i - 2 * S));
    else if (i < 4 * S)           cvt4(&g_w_mass[i - 3 * S],  massw  + (i - 3 * S));
    else if (i < 4 * S + H_ * H_) cvt4(&g_w_mass2[i - 4 * S], mass2w + (i - 4 * S));
    else {
        const int j = i - 4 * S - H_ * H_;
        if (j < O_ * H_)                  cvt4(&g_w_out[j], outw + j);
        else if (j < O_ * H_ + B_ * LAT_) cvt4(&g_enc_h[j - O_ * H_], ench_f + (j - O_ * H_));
        else if (j < O_ * H_ + 2 * B_ * LAT_)
            cvt4(&g_enc_o[j - O_ * H_ - B_ * LAT_], enco_f + (j - O_ * H_ - B_ * LAT_));
    }
}

__global__ void build_wcat(const float* __restrict__ W_ih, const float* __restrict__ W_hh,
                           const float* __restrict__ b_ih, const float* __restrict__ b_hh) {
    const int idx8 = blockIdx.x * blockDim.x + threadIdx.x;   // 1048576 chunks of 8
    const int np = idx8 >> 8;
    const int kc = (idx8 & 255) << 3;
    const int j = np >> 2, gg = np & 3;
    const int srow = gg * 1024 + j;
    const float* src = (kc < 1024) ? (W_ih + (size_t)srow * 1024 + kc)
                                   : (W_hh + (size_t)srow * 1024 + kc - 1024);
    float4 f0 = ((const float4*)src)[0];
    float4 f1 = ((const float4*)src)[1];
    __half2 h[4] = { __floats2half2_rn(f0.x, f0.y), __floats2half2_rn(f0.z, f0.w),
                     __floats2half2_rn(f1.x, f1.y), __floats2half2_rn(f1.z, f1.w) };
    *(uint4*)&g_Wcat[(size_t)np * 2048 + kc] = *(uint4*)h;
    if (idx8 < 4096) {
        const int jj = idx8 >> 2, g2 = idx8 & 3;
        g_bperm[idx8] = b_ih[g2 * 1024 + jj] + b_hh[g2 * 1024 + jj];
    }
}

__global__ void x0a0_kernel(const float* __restrict__ st, const float* __restrict__ w,
                            const float* __restrict__ b) {
    int u = blockIdx.x * blockDim.x + threadIdx.x;
    if (u >= H_) return;
    float s = b[u];
#pragma unroll 4
    for (int k = 0; k < O_; k++) s += st[k] * w[u * O_ + k];
    __half r = __float2half(fmaxf(s, 0.f));
    for (int m = 0; m < B_; m++) g_A[0][m * 2048 + u] = r;
}

__global__ void heads_kernel(const float* __restrict__ w2, const float* __restrict__ b2,
                             const float* __restrict__ w3, const float* __restrict__ b3,
                             float* __restrict__ num, float* __restrict__ mass) {
    int m = blockIdx.x * (blockDim.x >> 5) + (threadIdx.x >> 5);
    int lane = threadIdx.x & 31;
    float d0 = 0.f, d1 = 0.f, d2 = 0.f;
    for (int k = lane; k < H_; k += 32) {
        float s = __half2float(g_s1[m * H_ + k]);
        float t = __half2float(g_m2[m * H_ + k]);
        d0 += s * w2[k];
        d1 += t * w3[k];
        d2 += t * w3[H_ + k];
    }
#pragma unroll
    for (int o = 16; o; o >>= 1) {
        d0 += __shfl_down_sync(0xffffffffu, d0, o);
        d1 += __shfl_down_sync(0xffffffffu, d1, o);
        d2 += __shfl_down_sync(0xffffffffu, d2, o);
    }
    if (lane == 0) {
        num[m] = fmaxf(d0 + b2[0], 0.f);
        float e0 = d1 + b3[0], e1 = d2 + b3[1];
        float mx = fmaxf(e0, e1);
        float p0 = expf(e0 - mx), p1 = expf(e1 - mx);
        float inv = 1.f / (p0 + p1);
        mass[m * 2 + 0] = p0 * inv;
        mass[m * 2 + 1] = p1 * inv;
    }
}

// ================= host launcher =================
extern "C" void kernel_launch(void* const* d_in, const int* in_sizes, int n_in,
                              void* d_out, int out_size) {
    const float* enc_out     = (const float*)d_in[0];
    const float* enc_hid     = (const float*)d_in[1];
    const float* start_token = (const float*)d_in[2];
    const float* lat2hid_w   = (const float*)d_in[3];
    const float* lat2hid_b   = (const float*)d_in[4];
    const float* lat2hid2_w  = (const float*)d_in[5];
    const float* lat2hid2_b  = (const float*)d_in[6];
    const float* emb_fc_w    = (const float*)d_in[7];
    const float* emb_fc_b    = (const float*)d_in[8];
    const float* W_ih        = (const float*)d_in[9];
    const float* W_hh        = (const float*)d_in[10];
    const float* b_ih        = (const float*)d_in[11];
    const float* b_hh        = (const float*)d_in[12];
    const float* out_w       = (const float*)d_in[13];
    const float* out_b       = (const float*)d_in[14];
    const float* fc_seq_w    = (const float*)d_in[15];
    const float* fc_seq_b    = (const float*)d_in[16];
    const float* fc_seq2_w   = (const float*)d_in[17];
    const float* fc_seq2_b   = (const float*)d_in[18];
    const float* fc_mass_w   = (const float*)d_in[19];
    const float* fc_mass_b   = (const float*)d_in[20];
    const float* fc_mass2_w  = (const float*)d_in[21];
    const float* fc_mass2_b  = (const float*)d_in[22];
    const float* fc_mass3_w  = (const float*)d_in[23];
    const float* fc_mass3_b  = (const float*)d_in[24];

    int T = (out_size - 2 * B_ * H_ - B_ - B_ * NPART_) / (B_ * O_);
    if (T < 1) T = 1;
    if (T > MAXT) T = MAXT;

    float* out  = (float*)d_out;
    float* dec  = out;
    float* hT   = out + (size_t)B_ * T * O_;
    float* cT   = hT + B_ * H_;
    float* num  = cT + B_ * H_;
    float* mass = num + B_;

    void* p;
    cudaGetSymbolAddress(&p, g_bperm);   float*  bperm = (float*)p;
    cudaGetSymbolAddress(&p, g_A);       __half* Abuf  = (__half*)p;
    cudaGetSymbolAddress(&p, g_hs);      __half* hsb   = (__half*)p;
    cudaGetSymbolAddress(&p, g_w_l2h);   __half* wl2h  = (__half*)p;
    cudaGetSymbolAddress(&p, g_w_l2h2);  __half* wl2h2 = (__half*)p;
    cudaGetSymbolAddress(&p, g_w_seq);   __half* wseq  = (__half*)p;
    cudaGetSymbolAddress(&p, g_w_mass);  __half* wmass = (__half*)p;
    cudaGetSymbolAddress(&p, g_w_mass2); __half* wmass2= (__half*)p;
    cudaGetSymbolAddress(&p, g_w_out);   __half* wout  = (__half*)p;
    cudaGetSymbolAddress(&p, g_enc_h);   __half* ench  = (__half*)p;
    cudaGetSymbolAddress(&p, g_enc_o);   __half* enco  = (__half*)p;
    cudaGetSymbolAddress(&p, g_s1);      __half* s1    = (__half*)p;
    cudaGetSymbolAddress(&p, g_m1);      __half* m1    = (__half*)p;
    cudaGetSymbolAddress(&p, g_m2);      __half* m2    = (__half*)p;

    cudaFuncSetAttribute(gemm_k<EPI_H0C0>,   cudaFuncAttributeMaxDynamicSharedMemorySize, SMEM_BYTES);
    cudaFuncSetAttribute(gemm_k<EPI_LRELU2>, cudaFuncAttributeMaxDynamicSharedMemorySize, SMEM_BYTES);
    cudaFuncSetAttribute(gemm_k<EPI_DEC>,    cudaFuncAttributeMaxDynamicSharedMemorySize, SMEM_BYTES);
    cudaFuncSetAttribute(lstm_persist,       cudaFuncAttributeMaxDynamicSharedMemorySize, PSMEM);

    // 0: conversions (vectorized)   1: LSTM weight permute (vectorized)   2: x0/A0
    prep_kernel<<<(PREP_N / 4 + 255) / 256, 256>>>(lat2hid_w, lat2hid2_w, fc_seq_w, fc_mass_w,
                                                   fc_mass2_w, out_w, enc_hid, enc_out);
    build_wcat<<<(4096 * 2048 / 8) / 256, 256>>>(W_ih, W_hh, b_ih, b_hh);
    x0a0_kernel<<<4, 256>>>(start_token, emb_fc_w, emb_fc_b);

    GemmArgs ga;
    // 3: h0 (z=0 -> A0[:,1024:2048]) + c0 (z=1 -> cT) in ONE launch
    ga = GemmArgs{}; ga.T = T;
    ga.A = ench; ga.Bw = wl2h; ga.Bw2 = wl2h2; ga.K = LAT_;
    ga.bias = lat2hid_b; ga.bias2 = lat2hid2_b;
    ga.a16 = Abuf; ga.c_state = cT;
    gemm_k<EPI_H0C0><<<dim3(H_ / BN, B_ / BM, 2), 256, SMEM_BYTES>>>(ga);

    // 4: persistent LSTM — all T steps, one launch
    lstm_persist<<<dim3(4096 / BN, B_ / BM), 256, PSMEM>>>(bperm, cT, hT, hsb, T);

    // 5: heads: fc_seq (z=0 -> s1) + fc_mass (z=1 -> m1)
    ga = GemmArgs{}; ga.T = T;
    ga.A = enco; ga.Bw = wseq; ga.Bw2 = wmass; ga.K = LAT_;
    ga.bias = fc_seq_b; ga.bias2 = fc_mass_b;
    ga.a16 = s1; ga.a16b = m1;
    gemm_k<EPI_LRELU2><<<dim3(H_ / BN, B_ / BM, 2), 256, SMEM_BYTES>>>(ga);

    // 6: decoder projection FUSED with fc_mass2
    {
        const int dec_ny = (T * B_) / BM;
        const int mass_ny = 16;
        ga = GemmArgs{}; ga.T = T;
        ga.A = hsb; ga.Bw = wout; ga.K = H_; ga.bias = out_b; ga.outf = dec;
        ga.A2 = m1; ga.Bw2 = wmass2; ga.bias2 = fc_mass2_b; ga.a16 = m2;
        ga.dec_ny = dec_ny;
        gemm_k<EPI_DEC><<<dim3(O_ / BN, dec_ny + mass_ny), 256, SMEM_BYTES>>>(ga);
    }

    // 7: scalar heads
    heads_kernel<<<32, 256>>>(fc_seq2_w, fc_seq2_b, fc_mass3_w, fc_mass3_b, num, mass);
}

// round 17
// speedup vs baseline: 1.5156x; 1.0015x over previous
#include <cuda_runtime.h>
#include <cuda_fp16.h>
#include <math.h>
#include <stdint.h>

#define B_    256
#define LAT_  512
#define H_    1024
#define O_    128
#define NPART_ 2
#define MAXT  128

// ---- aux mma.sync GEMM config ----
#define BM 128
#define BN 64
#define BK 32
#define STAGES 4
#define LDS 40
#define SMEM_BYTES (STAGES*(BM+BN)*LDS*2)
enum { EPI_LRELU16 = 0, EPI_H0C0, EPI_LRELU2, EPI_DEC };

// ---- persistent LSTM mainloop config (256 threads, 8 warps, 4 stages) ----
#define BK2   64
#define KH    4
#define ST2   4
#define LDS2  72
#define PSMEM (ST2*(BM+BN)*LDS2*2)   // 110592 B

// ---- device scratch ----
__device__ __align__(16) __half g_Wcat[4096u*2048u];
__device__ __align__(16) float  g_bperm[4096];
__device__ __align__(16) __half g_A[2][B_*2048];
__device__ __align__(16) __half g_hs[(size_t)MAXT*B_*H_];
__device__ __align__(16) __half g_w_l2h [H_*LAT_];
__device__ __align__(16) __half g_w_l2h2[H_*LAT_];
__device__ __align__(16) __half g_w_seq [H_*LAT_];
__device__ __align__(16) __half g_w_mass[H_*LAT_];
__device__ __align__(16) __half g_w_mass2[H_*H_];
__device__ __align__(16) __half g_w_out [O_*H_];
__device__ __align__(16) __half g_enc_h[B_*LAT_];
__device__ __align__(16) __half g_enc_o[B_*LAT_];
__device__ __align__(16) __half g_s1[B_*H_];
__device__ __align__(16) __half g_m1[B_*H_];
__device__ __align__(16) __half g_m2[B_*H_];

// per-my-group barrier state, 128B-separated
__device__ __align__(128) unsigned g_barc2[64];
__device__ __align__(128) unsigned g_barg2[64];

// ---- helpers ----
__device__ __forceinline__ uint32_t smem_u32(const void* p) {
    return (uint32_t)__cvta_generic_to_shared(p);
}
__device__ __forceinline__ void cp16(uint32_t s, const void* g) {
    asm volatile("cp.async.cg.shared.global [%0], [%1], 16;" :: "r"(s), "l"(g));
}
__device__ __forceinline__ void ldsm4(unsigned &r0, unsigned &r1, unsigned &r2, unsigned &r3,
                                      uint32_t addr) {
    asm volatile("ldmatrix.sync.aligned.m8n8.x4.shared.b16 {%0,%1,%2,%3}, [%4];"
                 : "=r"(r0), "=r"(r1), "=r"(r2), "=r"(r3) : "r"(addr));
}
__device__ __forceinline__ void mma16816(float* c, const unsigned* a, unsigned b0, unsigned b1) {
    asm volatile("mma.sync.aligned.m16n8k16.row.col.f32.f16.f16.f32 "
                 "{%0,%1,%2,%3}, {%4,%5,%6,%7}, {%8,%9}, {%0,%1,%2,%3};"
                 : "+f"(c[0]), "+f"(c[1]), "+f"(c[2]), "+f"(c[3])
                 : "r"(a[0]), "r"(a[1]), "r"(a[2]), "r"(a[3]), "r"(b0), "r"(b1));
}
__device__ __forceinline__ float lrelu(float x) { return x > 0.f ? x : 0.01f * x; }
__device__ __forceinline__ float sigm(float x) { return 1.f / (1.f + __expf(-x)); }

// per-group barrier: only the 64 CTAs sharing blockIdx.y must sync
__device__ __forceinline__ void grid_sync_group(unsigned nb, int grp) {
    unsigned* cc = &g_barc2[grp * 32];
    unsigned* gg = &g_barg2[grp * 32];
    __syncthreads();
    if (threadIdx.x == 0) {
        __threadfence();
        unsigned target;
        asm volatile("ld.volatile.global.u32 %0, [%1];" : "=r"(target) : "l"(gg));
        unsigned old = atomicAdd(cc, 1u);
        if (old == nb - 1u) {
            *cc = 0u;
            __threadfence();
            atomicAdd(gg, 1u);
        } else {
            unsigned cur;
            do {
                asm volatile("ld.volatile.global.u32 %0, [%1];" : "=r"(cur) : "l"(gg));
            } while ((int)(cur - target) <= 0);
        }
        __threadfence();
    }
    __syncthreads();
}

// ================= persistent LSTM (exact round-8 schedule, split barrier) =================
__global__ void __launch_bounds__(256, 1)
lstm_persist(const float* __restrict__ bias, float* __restrict__ cst,
             float* __restrict__ hT, __half* __restrict__ hs_all, int T) {
    extern __shared__ __half sm[];
    __half* sA = sm;                        // ST2 * BM * LDS2
    __half* sB = sm + ST2 * BM * LDS2;      // ST2 * BN * LDS2
    __half* hstage = sm;                    // 128 x 24 halfs, reuses sA after mainloop

    const int tid  = threadIdx.x;
    const int lane = tid & 31;
    const int wid  = tid >> 5;
    const int warpM = (wid & 3) * 32;
    const int warpN = (wid >> 2) * 32;
    const int mbase = blockIdx.y * BM;
    const int nbase = blockIdx.x * BN;
    const __half* Bg = g_Wcat + (size_t)nbase * 2048;

    const uint32_t smA = smem_u32(sA);
    const uint32_t smB = smem_u32(sB);
    const int l7  = lane & 7;
    const int grp = lane >> 3;
    const uint32_t aL = smA + (uint32_t)(((warpM + (grp & 1) * 8 + l7) * LDS2 + (grp >> 1) * 8) * 2);
    const uint32_t bL = smB + (uint32_t)(((warpN + (grp >> 1) * 8 + l7) * LDS2 + (grp & 1) * 8) * 2);
    const int r = lane >> 2, q = lane & 3;
    const unsigned NBG = gridDim.x;
    const int myg = blockIdx.y;
    const int KT = 2048 / BK2;              // 32
    const bool evenq = !(q & 1);

    float creg[2][4];
#pragma unroll
    for (int mi = 0; mi < 2; mi++)
#pragma unroll
        for (int ni = 0; ni < 4; ni++) {
            const int m = mbase + warpM + mi * 16 + r + (evenq ? 0 : 8);
            const int u = (nbase + warpN + ni * 8 + 2 * (q & ~1)) >> 2;
            creg[mi][ni] = cst[(size_t)m * H_ + u];
        }

    auto issue_B = [&](int kt, int s) {
        const int ko = kt * BK2;
#pragma unroll
        for (int j = 0; j < 2; j++) {
            const int c = tid + j * 256;
            const int row = c >> 3, ch = c & 7;
            cp16(smB + (uint32_t)(((s * BN + row) * LDS2 + ch * 8) * 2),
                 Bg + (size_t)row * 2048 + ko + ch * 8);
        }
    };

    for (int t = 0; t < T; t++) {
        const __half* Ag = g_A[t & 1] + (size_t)mbase * 2048;
        __half* Anext = g_A[(t + 1) & 1];
        __half* hs = hs_all + (size_t)t * B_ * H_;

        auto issue_A = [&](int kt, int s) {
            const int ko = kt * BK2;
#pragma unroll
            for (int j = 0; j < 4; j++) {
                const int c = tid + j * 256;
                const int row = c >> 3, ch = c & 7;
                cp16(smA + (uint32_t)(((s * BM + row) * LDS2 + ch * 8) * 2),
                     Ag + (size_t)row * 2048 + ko + ch * 8);
            }
        };

        auto load_frag = [&](int s, int kh, unsigned (&fa)[2][4], unsigned (&fb)[2][4]) {
            const uint32_t ab = aL + (uint32_t)(s * BM * LDS2 * 2) + kh * 32;
            ldsm4(fa[0][0], fa[0][1], fa[0][2], fa[0][3], ab);
            ldsm4(fa[1][0], fa[1][1], fa[1][2], fa[1][3], ab + 16 * LDS2 * 2);
            const uint32_t bb = bL + (uint32_t)(s * BN * LDS2 * 2) + kh * 32;
            ldsm4(fb[0][0], fb[0][1], fb[0][2], fb[0][3], bb);
            ldsm4(fb[1][0], fb[1][1], fb[1][2], fb[1][3], bb + 16 * LDS2 * 2);
        };

        float ac[2][4][4];
#pragma unroll
        for (int i = 0; i < 2; i++)
#pragma unroll
            for (int j = 0; j < 4; j++)
#pragma unroll
                for (int k = 0; k < 4; k++) ac[i][j][k] = 0.f;

        unsigned fa[2][2][4], fb[2][2][4];

        if (t == 0) {
            issue_A(0, 0); issue_B(0, 0); asm volatile("cp.async.commit_group;");
            issue_A(1, 1); issue_B(1, 1); asm volatile("cp.async.commit_group;");
            issue_A(2, 2); issue_B(2, 2); asm volatile("cp.async.commit_group;");
        } else {
            issue_A(0, 0); asm volatile("cp.async.commit_group;");
            issue_A(1, 1); asm volatile("cp.async.commit_group;");
            issue_A(2, 2); asm volatile("cp.async.commit_group;");
        }
        asm volatile("cp.async.wait_group %0;" :: "n"(ST2 - 2));
        __syncthreads();
        load_frag(0, 0, fa[0], fb[0]);
        int cur = 0;

        for (int kt = 0; kt < KT; kt++) {
            const int s = kt % ST2;
#pragma unroll
            for (int kh = 0; kh < KH; kh++) {
                if (kh < KH - 1) {
                    load_frag(s, kh + 1, fa[cur ^ 1], fb[cur ^ 1]);
                } else {
                    const int nk = kt + ST2 - 1;
                    if (nk < KT) {
                        issue_A(nk, nk % ST2);
                        issue_B(nk, nk % ST2);
                    }
                    asm volatile("cp.async.commit_group;");
                    asm volatile("cp.async.wait_group %0;" :: "n"(ST2 - 2));
                    __syncthreads();
                    if (kt + 1 < KT)
                        load_frag((kt + 1) % ST2, 0, fa[cur ^ 1], fb[cur ^ 1]);
                }
                mma16816(ac[0][0], fa[cur][0], fb[cur][0][0], fb[cur][0][1]);
                mma16816(ac[0][1], fa[cur][0], fb[cur][0][2], fb[cur][0][3]);
                mma16816(ac[0][2], fa[cur][0], fb[cur][1][0], fb[cur][1][1]);
                mma16816(ac[0][3], fa[cur][0], fb[cur][1][2], fb[cur][1][3]);
                mma16816(ac[1][0], fa[cur][1], fb[cur][0][0], fb[cur][0][1]);
                mma16816(ac[1][1], fa[cur][1], fb[cur][0][2], fb[cur][0][3]);
                mma16816(ac[1][2], fa[cur][1], fb[cur][1][0], fb[cur][1][1]);
                mma16816(ac[1][3], fa[cur][1], fb[cur][1][2], fb[cur][1][3]);
                cur ^= 1;
            }
        }

        const int last = (t == T - 1);
        if (!last) {
            issue_B(0, 0);
            issue_B(1, 1);
            issue_B(2, 2);
        }

#pragma unroll
        for (int mi = 0; mi < 2; mi++)
#pragma unroll
            for (int ni = 0; ni < 4; ni++) {
                float c0 = ac[mi][ni][0], c1 = ac[mi][ni][1];
                float c2 = ac[mi][ni][2], c3 = ac[mi][ni][3];
                float p0 = __shfl_xor_sync(0xffffffffu, c0, 1);
                float p1 = __shfl_xor_sync(0xffffffffu, c1, 1);
                float p2 = __shfl_xor_sync(0xffffffffu, c2, 1);
                float p3 = __shfl_xor_sync(0xffffffffu, c3, 1);
                const int mloc = warpM + mi * 16 + r + (evenq ? 0 : 8);
                const int uloc = (warpN + ni * 8 + 2 * (q & ~1)) >> 2;
                float gi = evenq ? c0 : p2;
                float gf = evenq ? c1 : p3;
                float gg = evenq ? p0 : c2;
                float go = evenq ? p1 : c3;
                const float4 bb = ((const float4*)bias)[(nbase >> 2) + uloc];
                gi += bb.x; gf += bb.y; gg += bb.z; go += bb.w;
                const float i_ = sigm(gi), f_ = sigm(gf);
                const float g_ = tanhf(gg), o_ = sigm(go);
                const float cc = f_ * creg[mi][ni] + i_ * g_;
                creg[mi][ni] = cc;
                const float h = o_ * tanhf(cc);
                hstage[mloc * 24 + uloc] = __float2half(h);
                if (last) {
                    hT [(size_t)(mbase + mloc) * H_ + (nbase >> 2) + uloc] = h;
                    cst[(size_t)(mbase + mloc) * H_ + (nbase >> 2) + uloc] = cc;
                }
            }
        __syncthreads();

        {
            const int m2  = tid >> 1;
            const int off = (tid & 1) * 8;
            uint4 hv = *(uint4*)&hstage[m2 * 24 + off];
            __half2* hh = (__half2*)&hv;
            uint4 rv; __half2* rr = (__half2*)&rv;
            const __half2 z2 = __floats2half2_rn(0.f, 0.f);
#pragma unroll
            for (int j = 0; j < 4; j++) rr[j] = __hmax2(hh[j], z2);
            const int mg = mbase + m2;
            const int ub = (nbase >> 2) + off;
            *(uint4*)&Anext[(size_t)mg * 2048 + ub]        = rv;
            *(uint4*)&Anext[(size_t)mg * 2048 + 1024 + ub] = hv;
            *(uint4*)&hs[(size_t)mg * H_ + ub]             = hv;
        }

        if (!last) grid_sync_group(NBG, myg);
    }
}

// ================= aux mma.sync GEMM (z-merged + decoder/mass2 fused) =================
struct GemmArgs {
    const __half* A;
    const __half* Bw;
    const __half* Bw2;
    const __half* A2;
    int K;
    const float* bias;
    const float* bias2;
    float*  c_state;
    __half* a16;
    __half* a16b;
    float*  outf;
    int T;
    int dec_ny;
};

template<int EPI>
__global__ void __launch_bounds__(256) gemm_k(GemmArgs g) {
    extern __shared__ __half sm[];
    __half* sA = sm;
    __half* sB = sm + STAGES * BM * LDS;

    const int tid  = threadIdx.x;
    const int lane = tid & 31;
    const int wid  = tid >> 5;
    const int warpM = (wid & 3) * 32;
    const int warpN = (wid >> 2) * 32;
    const int zz   = blockIdx.z;
    const int K = g.K;

    int mbase = blockIdx.y * BM;
    int nbase = blockIdx.x * BN;
    const __half* Bw   = zz ? g.Bw2  : g.Bw;
    const float*  bias = zz ? g.bias2 : g.bias;
    const __half* Aptr = g.A;
    bool massm = false;
    if (EPI == EPI_DEC && blockIdx.y >= g.dec_ny) {
        massm = true;
        const int idx = (blockIdx.y - g.dec_ny) * 2 + blockIdx.x;
        nbase = (idx & 15) * BN;
        mbase = (idx >> 4) * BM;
        Aptr = g.A2;
        Bw   = g.Bw2;
        bias = g.bias2;
    }
    const __half* Ag = Aptr + (size_t)mbase * K;
    const __half* Bg = Bw   + (size_t)nbase * K;

    const uint32_t smA = smem_u32(sA);
    const uint32_t smB = smem_u32(sB);

    const int l7  = lane & 7;
    const int grp = lane >> 3;
    const uint32_t aL = smA + (uint32_t)(((warpM + (grp & 1) * 8 + l7) * LDS + (grp >> 1) * 8) * 2);
    const uint32_t bL = smB + (uint32_t)(((warpN + (grp >> 1) * 8 + l7) * LDS + (grp & 1) * 8) * 2);

    const int aRow = tid >> 1, aCh = (tid & 1) * 2;
    const int bRow = tid >> 2, bCh = tid & 3;

    auto issue_stage = [&](int kt, int s) {
        const int ko = kt * BK;
        uint32_t sa = smA + (uint32_t)(((s * BM + aRow) * LDS + aCh * 8) * 2);
        const __half* gp = Ag + (size_t)aRow * K + ko + aCh * 8;
        cp16(sa, gp);
        cp16(sa + 16, gp + 8);
        uint32_t sb = smB + (uint32_t)(((s * BN + bRow) * LDS + bCh * 8) * 2);
        cp16(sb, Bg + (size_t)bRow * K + ko + bCh * 8);
        asm volatile("cp.async.commit_group;");
    };

    float ac[2][4][4];
#pragma unroll
    for (int i = 0; i < 2; i++)
#pragma unroll
        for (int j = 0; j < 4; j++)
#pragma unroll
            for (int k = 0; k < 4; k++) ac[i][j][k] = 0.f;

    const int KT = K / BK;
#pragma unroll
    for (int s = 0; s < STAGES - 1; s++) issue_stage(s, s);

    for (int kt = 0; kt < KT; kt++) {
        asm volatile("cp.async.wait_group %0;" :: "n"(STAGES - 2));
        __syncthreads();
        const int nk = kt + STAGES - 1;
        if (nk < KT) issue_stage(nk, nk % STAGES);
        else asm volatile("cp.async.commit_group;");

        const int s = kt % STAGES;
#pragma unroll
        for (int kh = 0; kh < 2; kh++) {
            unsigned a0[4], a1[4], b0[4], b1[4];
            const uint32_t ab = aL + (uint32_t)(s * BM * LDS * 2) + kh * 32;
            ldsm4(a0[0], a0[1], a0[2], a0[3], ab);
            ldsm4(a1[0], a1[1], a1[2], a1[3], ab + 16 * LDS * 2);
            const uint32_t bb = bL + (uint32_t)(s * BN * LDS * 2) + kh * 32;
            ldsm4(b0[0], b0[1], b0[2], b0[3], bb);
            ldsm4(b1[0], b1[1], b1[2], b1[3], bb + 16 * LDS * 2);

            mma16816(ac[0][0], a0, b0[0], b0[1]);
            mma16816(ac[0][1], a0, b0[2], b0[3]);
            mma16816(ac[0][2], a0, b1[0], b1[1]);
            mma16816(ac[0][3], a0, b1[2], b1[3]);
            mma16816(ac[1][0], a1, b0[0], b0[1]);
            mma16816(ac[1][1], a1, b0[2], b0[3]);
            mma16816(ac[1][2], a1, b1[0], b1[1]);
            mma16816(ac[1][3], a1, b1[2], b1[3]);
        }
    }

    const int r = lane >> 2, q = lane & 3;
#pragma unroll
    for (int mi = 0; mi < 2; mi++)
#pragma unroll
        for (int ni = 0; ni < 4; ni++) {
            const int col  = nbase + warpN + ni * 8 + 2 * q;
            const int row0 = mbase + warpM + mi * 16 + r;
            const int row1 = row0 + 8;
            const float v00 = ac[mi][ni][0], v01 = ac[mi][ni][1];
            const float v10 = ac[mi][ni][2], v11 = ac[mi][ni][3];
            const float b0f = bias[col], b1f = bias[col + 1];
            if (EPI == EPI_LRELU16) {
                *(__half2*)&g.a16[row0 * H_ + col] =
                    __floats2half2_rn(lrelu(v00 + b0f), lrelu(v01 + b1f));
                *(__half2*)&g.a16[row1 * H_ + col] =
                    __floats2half2_rn(lrelu(v10 + b0f), lrelu(v11 + b1f));
            } else if (EPI == EPI_LRELU2) {
                __half* dst = zz ? g.a16b : g.a16;
                *(__half2*)&dst[row0 * H_ + col] =
                    __floats2half2_rn(lrelu(v00 + b0f), lrelu(v01 + b1f));
                *(__half2*)&dst[row1 * H_ + col] =
                    __floats2half2_rn(lrelu(v10 + b0f), lrelu(v11 + b1f));
            } else if (EPI == EPI_H0C0) {
                if (zz == 0) {
                    float a0f = lrelu(v00 + b0f), a1f = lrelu(v01 + b1f);
                    float a2f = lrelu(v10 + b0f), a3f = lrelu(v11 + b1f);
                    *(__half2*)&g.a16[row0 * 2048 + 1024 + col] = __floats2half2_rn(a0f, a1f);
                    *(__half2*)&g.a16[row1 * 2048 + 1024 + col] = __floats2half2_rn(a2f, a3f);
                } else {
                    *(float2*)&g.c_state[row0 * H_ + col] =
                        make_float2(lrelu(v00 + b0f), lrelu(v01 + b1f));
                    *(float2*)&g.c_state[row1 * H_ + col] =
                        make_float2(lrelu(v10 + b0f), lrelu(v11 + b1f));
                }
            } else { // EPI_DEC (fused with mass2)
                if (massm) {
                    *(__half2*)&g.a16[row0 * H_ + col] =
                        __floats2half2_rn(lrelu(v00 + b0f), lrelu(v01 + b1f));
                    *(__half2*)&g.a16[row1 * H_ + col] =
                        __floats2half2_rn(lrelu(v10 + b0f), lrelu(v11 + b1f));
                } else {
                    const int bb0 = row0 & 255, tt0 = row0 >> 8;
                    const int bb1 = row1 & 255, tt1 = row1 >> 8;
                    *(float2*)&g.outf[(size_t)bb0 * g.T * O_ + tt0 * O_ + col] =
                        make_float2(v00 + b0f, v01 + b1f);
                    *(float2*)&g.outf[(size_t)bb1 * g.T * O_ + tt1 * O_ + col] =
                        make_float2(v10 + b0f, v11 + b1f);
                }
            }
        }
}

// ================= setup kernels (vectorized) =================
#define PREP_N (4*H_*LAT_ + H_*H_ + O_*H_ + 2*B_*LAT_)

__device__ __forceinline__ void cvt4(__half* dst, const float* src) {
    float4 f = *(const float4*)src;
    __half2 h[2] = { __floats2half2_rn(f.x, f.y), __floats2half2_rn(f.z, f.w) };
    *(uint2*)dst = *(uint2*)h;
}

__global__ void prep_kernel(const float* __restrict__ l2h,  const float* __restrict__ l2h2,
                            const float* __restrict__ seqw, const float* __restrict__ massw,
                            const float* __restrict__ mass2w, const float* __restrict__ outw,
                            const float* __restrict__ ench_f, const float* __restrict__ enco_f) {
    const int i = (blockIdx.x * blockDim.x + threadIdx.x) * 4;
    const int S = H_ * LAT_;
    if (i < S)                    cvt4(&g_w_l2h [i],          l2h    + i);
    else if (i < 2 * S)           cvt4(&g_w_l2h2[i - S],      l2h2   + (i - S));
    else if (i < 3 * S)           cvt4(&g_w_seq [i - 2 * S],  seqw   + (i - 2 * S));
    else if (i < 4 * S)           cvt4(&g_w_mass[i - 3 * S],  massw  + (i - 3 * S));
    else if (i < 4 * S + H_ * H_) cvt4(&g_w_mass2[i - 4 * S], mass2w + (i - 4 * S));
    else {
        const int j = i - 4 * S - H_ * H_;
        if (j < O_ * H_)                  cvt4(&g_w_out[j], outw + j);
        else if (j < O_ * H_ + B_ * LAT_) cvt4(&g_enc_h[j - O_ * H_], ench_f + (j - O_ * H_));
        else if (j < O_ * H_ + 2 * B_ * LAT_)
            cvt4(&g_enc_o[j - O_ * H_ - B_ * LAT_], enco_f + (j - O_ * H_ - B_ * LAT_));
    }
}

__global__ void build_wcat(const float* __restrict__ W_ih, const float* __restrict__ W_hh,
                           const float* __restrict__ b_ih, const float* __restrict__ b_hh) {
    const int idx8 = blockIdx.x * blockDim.x + threadIdx.x;
    const int np = idx8 >> 8;
    const int kc = (idx8 & 255) << 3;
    const int j = np >> 2, gg = np & 3;
    const int srow = gg * 1024 + j;
    const float* src = (kc < 1024) ? (W_ih + (size_t)srow * 1024 + kc)
                                   : (W_hh + (size_t)srow * 1024 + kc - 1024);
    float4 f0 = ((const float4*)src)[0];
    float4 f1 = ((const float4*)src)[1];
    __half2 h[4] = { __floats2half2_rn(f0.x, f0.y), __floats2half2_rn(f0.z, f0.w),
                     __floats2half2_rn(f1.x, f1.y), __floats2half2_rn(f1.z, f1.w) };
    *(uint4*)&g_Wcat[(size_t)np * 2048 + kc] = *(uint4*)h;
    if (idx8 < 4096) {
        const int jj = idx8 >> 2, g2 = idx8 & 3;
        g_bperm[idx8] = b_ih[g2 * 1024 + jj] + b_hh[g2 * 1024 + jj];
    }
}

__global__ void x0a0_kernel(const float* __restrict__ st, const float* __restrict__ w,
                            const float* __restrict__ b) {
    int u = blockIdx.x * blockDim.x + threadIdx.x;
    if (u >= H_) return;
    float s = b[u];
#pragma unroll 4
    for (int k = 0; k < O_; k++) s += st[k] * w[u * O_ + k];
    __half r = __float2half(fmaxf(s, 0.f));
    for (int m = 0; m < B_; m++) g_A[0][m * 2048 + u] = r;
}

__global__ void heads_kernel(const float* __restrict__ w2, const float* __restrict__ b2,
                             const float* __restrict__ w3, const float* __restrict__ b3,
                             float* __restrict__ num, float* __restrict__ mass) {
    int m = blockIdx.x * (blockDim.x >> 5) + (threadIdx.x >> 5);
    int lane = threadIdx.x & 31;
    float d0 = 0.f, d1 = 0.f, d2 = 0.f;
    for (int k = lane; k < H_; k += 32) {
        float s = __half2float(g_s1[m * H_ + k]);
        float t = __half2float(g_m2[m * H_ + k]);
        d0 += s * w2[k];
        d1 += t * w3[k];
        d2 += t * w3[H_ + k];
    }
#pragma unroll
    for (int o = 16; o; o >>= 1) {
        d0 += __shfl_down_sync(0xffffffffu, d0, o);
        d1 += __shfl_down_sync(0xffffffffu, d1, o);
        d2 += __shfl_down_sync(0xffffffffu, d2, o);
    }
    if (lane == 0) {
        num[m] = fmaxf(d0 + b2[0], 0.f);
        float e0 = d1 + b3[0], e1 = d2 + b3[1];
        float mx = fmaxf(e0, e1);
        float p0 = expf(e0 - mx), p1 = expf(e1 - mx);
        float inv = 1.f / (p0 + p1);
        mass[m * 2 + 0] = p0 * inv;
        mass[m * 2 + 1] = p1 * inv;
    }
}

// ================= host launcher =================
extern "C" void kernel_launch(void* const* d_in, const int* in_sizes, int n_in,
                              void* d_out, int out_size) {
    const float* enc_out     = (const float*)d_in[0];
    const float* enc_hid     = (const float*)d_in[1];
    const float* start_token = (const float*)d_in[2];
    const float* lat2hid_w   = (const float*)d_in[3];
    const float* lat2hid_b   = (const float*)d_in[4];
    const float* lat2hid2_w  = (const float*)d_in[5];
    const float* lat2hid2_b  = (const float*)d_in[6];
    const float* emb_fc_w    = (const float*)d_in[7];
    const float* emb_fc_b    = (const float*)d_in[8];
    const float* W_ih        = (const float*)d_in[9];
    const float* W_hh        = (const float*)d_in[10];
    const float* b_ih        = (const float*)d_in[11];
    const float* b_hh        = (const float*)d_in[12];
    const float* out_w       = (const float*)d_in[13];
    const float* out_b       = (const float*)d_in[14];
    const float* fc_seq_w    = (const float*)d_in[15];
    const float* fc_seq_b    = (const float*)d_in[16];
    const float* fc_seq2_w   = (const float*)d_in[17];
    const float* fc_seq2_b   = (const float*)d_in[18];
    const float* fc_mass_w   = (const float*)d_in[19];
    const float* fc_mass_b   = (const float*)d_in[20];
    const float* fc_mass2_w  = (const float*)d_in[21];
    const float* fc_mass2_b  = (const float*)d_in[22];
    const float* fc_mass3_w  = (const float*)d_in[23];
    const float* fc_mass3_b  = (const float*)d_in[24];

    int T = (out_size - 2 * B_ * H_ - B_ - B_ * NPART_) / (B_ * O_);
    if (T < 1) T = 1;
    if (T > MAXT) T = MAXT;

    float* out  = (float*)d_out;
    float* dec  = out;
    float* hT   = out + (size_t)B_ * T * O_;
    float* cT   = hT + B_ * H_;
    float* num  = cT + B_ * H_;
    float* mass = num + B_;

    void* p;
    cudaGetSymbolAddress(&p, g_bperm);   float*  bperm = (float*)p;
    cudaGetSymbolAddress(&p, g_A);       __half* Abuf  = (__half*)p;
    cudaGetSymbolAddress(&p, g_hs);      __half* hsb   = (__half*)p;
    cudaGetSymbolAddress(&p, g_w_l2h);   __half* wl2h  = (__half*)p;
    cudaGetSymbolAddress(&p, g_w_l2h2);  __half* wl2h2 = (__half*)p;
    cudaGetSymbolAddress(&p, g_w_seq);   __half* wseq  = (__half*)p;
    cudaGetSymbolAddress(&p, g_w_mass);  __half* wmass = (__half*)p;
    cudaGetSymbolAddress(&p, g_w_mass2); __half* wmass2= (__half*)p;
    cudaGetSymbolAddress(&p, g_w_out);   __half* wout  = (__half*)p;
    cudaGetSymbolAddress(&p, g_enc_h);   __half* ench  = (__half*)p;
    cudaGetSymbolAddress(&p, g_enc_o);   __half* enco  = (__half*)p;
    cudaGetSymbolAddress(&p, g_s1);      __half* s1    = (__half*)p;
    cudaGetSymbolAddress(&p, g_m1);      __half* m1    = (__half*)p;
    cudaGetSymbolAddress(&p, g_m2);      __half* m2    = (__half*)p;

    cudaFuncSetAttribute(gemm_k<EPI_H0C0>,   cudaFuncAttributeMaxDynamicSharedMemorySize, SMEM_BYTES);
    cudaFuncSetAttribute(gemm_k<EPI_LRELU2>, cudaFuncAttributeMaxDynamicSharedMemorySize, SMEM_BYTES);
    cudaFuncSetAttribute(gemm_k<EPI_DEC>,    cudaFuncAttributeMaxDynamicSharedMemorySize, SMEM_BYTES);
    cudaFuncSetAttribute(lstm_persist,       cudaFuncAttributeMaxDynamicSharedMemorySize, PSMEM);

    // side stream + fork/join events (leaked: destroying during capture is illegal;
    // a handful of calls per process -> negligible)
    cudaStream_t s2;
    cudaStreamCreate(&s2);
    cudaEvent_t evF, evP, evA, evB;
    cudaEventCreateWithFlags(&evF, cudaEventDisableTiming);
    cudaEventCreateWithFlags(&evP, cudaEventDisableTiming);
    cudaEventCreateWithFlags(&evA, cudaEventDisableTiming);
    cudaEventCreateWithFlags(&evB, cudaEventDisableTiming);

    // fork s2 off the origin stream
    cudaEventRecord(evF, 0);
    cudaStreamWaitEvent(s2, evF, 0);

    // s2: wcat + x0a0 (depend only on raw inputs)
    build_wcat<<<(4096 * 2048 / 8) / 256, 256, 0, s2>>>(W_ih, W_hh, b_ih, b_hh);
    x0a0_kernel<<<4, 256, 0, s2>>>(start_token, emb_fc_w, emb_fc_b);
    cudaEventRecord(evA, s2);

    // default: conversions, then H0C0 (needs prep)
    prep_kernel<<<(PREP_N / 4 + 255) / 256, 256>>>(lat2hid_w, lat2hid2_w, fc_seq_w, fc_mass_w,
                                                   fc_mass2_w, out_w, enc_hid, enc_out);
    cudaEventRecord(evP, 0);

    GemmArgs ga;
    ga = GemmArgs{}; ga.T = T;
    ga.A = ench; ga.Bw = wl2h; ga.Bw2 = wl2h2; ga.K = LAT_;
    ga.bias = lat2hid_b; ga.bias2 = lat2hid2_b;
    ga.a16 = Abuf; ga.c_state = cT;
    gemm_k<EPI_H0C0><<<dim3(H_ / BN, B_ / BM, 2), 256, SMEM_BYTES>>>(ga);

    // s2: heads GEMM (needs prep only) — runs concurrent with H0C0 + LSTM on idle SMs
    cudaStreamWaitEvent(s2, evP, 0);
    GemmArgs gh;
    gh = GemmArgs{}; gh.T = T;
    gh.A = enco; gh.Bw = wseq; gh.Bw2 = wmass; gh.K = LAT_;
    gh.bias = fc_seq_b; gh.bias2 = fc_mass_b;
    gh.a16 = s1; gh.a16b = m1;
    gemm_k<EPI_LRELU2><<<dim3(H_ / BN, B_ / BM, 2), 256, SMEM_BYTES, s2>>>(gh);
    cudaEventRecord(evB, s2);

    // default: persistent LSTM (needs wcat + x0a0 from s2, and H0C0)
    cudaStreamWaitEvent(0, evA, 0);
    lstm_persist<<<dim3(4096 / BN, B_ / BM), 256, PSMEM>>>(bperm, cT, hT, hsb, T);

    // join: decoder needs m1 from s2
    cudaStreamWaitEvent(0, evB, 0);
    {
        const int dec_ny = (T * B_) / BM;
        const int mass_ny = 16;
        ga = GemmArgs{}; ga.T = T;
        ga.A = hsb; ga.Bw = wout; ga.K = H_; ga.bias = out_b; ga.outf = dec;
        ga.A2 = m1; ga.Bw2 = wmass2; ga.bias2 = fc_mass2_b; ga.a16 = m2;
        ga.dec_ny = dec_ny;
        gemm_k<EPI_DEC><<<dim3(O_ / BN, dec_ny + mass_ny), 256, SMEM_BYTES>>>(ga);
    }

    heads_kernel<<<32, 256>>>(fc_seq2_w, fc_seq2_b, fc_mass3_w, fc_mass3_b, num, mass);
}